// round 1
// baseline (speedup 1.0000x reference)
#include <cuda_runtime.h>

#define DQ   512
#define H1Q  16
#define CQ   40
#define N_MAX 100000

// Scratch (device globals: no allocation allowed in kernel_launch)
__device__ float g_X1[N_MAX * H1Q];  // H @ W1
__device__ float g_Y1[N_MAX * H1Q];  // A @ X1
__device__ float g_Y2[N_MAX * H1Q];  // A @ relu(Y1 + b1)

// ---------------------------------------------------------------------------
// Zero the two scatter targets
// ---------------------------------------------------------------------------
__global__ void zero_kernel(int n_each_f4) {
    float4 z = make_float4(0.f, 0.f, 0.f, 0.f);
    float4* y1 = reinterpret_cast<float4*>(g_Y1);
    float4* y2 = reinterpret_cast<float4*>(g_Y2);
    for (int j = blockIdx.x * blockDim.x + threadIdx.x; j < n_each_f4;
         j += gridDim.x * blockDim.x) {
        y1[j] = z;
        y2[j] = z;
    }
}

// ---------------------------------------------------------------------------
// K1: X1 = H @ W1   [N,512] @ [512,16]  — warp per row, W1 in smem (stride 20)
// ---------------------------------------------------------------------------
__global__ void gemm1_kernel(const float* __restrict__ Hm,
                             const float* __restrict__ W1, int n) {
    __shared__ float sW[DQ * 20];
    for (int i = threadIdx.x; i < DQ * H1Q; i += blockDim.x) {
        int k = i / H1Q, c = i % H1Q;
        sW[k * 20 + c] = W1[i];
    }
    __syncthreads();

    int warp = threadIdx.x >> 5;
    int lane = threadIdx.x & 31;
    int row  = blockIdx.x * 4 + warp;
    if (row >= n) return;

    float acc[16];
#pragma unroll
    for (int c = 0; c < 16; c++) acc[c] = 0.f;

    const float* hrow = Hm + (size_t)row * DQ;
#pragma unroll
    for (int m = 0; m < 16; m++) {
        int k  = m * 32 + lane;          // coalesced 128B per warp-iter
        float h = hrow[k];
        const float4* w = reinterpret_cast<const float4*>(&sW[k * 20]);
#pragma unroll
        for (int j = 0; j < 4; j++) {
            float4 w4 = w[j];
            acc[4 * j + 0] = fmaf(h, w4.x, acc[4 * j + 0]);
            acc[4 * j + 1] = fmaf(h, w4.y, acc[4 * j + 1]);
            acc[4 * j + 2] = fmaf(h, w4.z, acc[4 * j + 2]);
            acc[4 * j + 3] = fmaf(h, w4.w, acc[4 * j + 3]);
        }
    }
    // full butterfly reduce: every lane ends with the complete sums
#pragma unroll
    for (int off = 16; off; off >>= 1) {
#pragma unroll
        for (int c = 0; c < 16; c++)
            acc[c] += __shfl_xor_sync(0xffffffffu, acc[c], off);
    }
    if (lane == 0) {
        float4* o = reinterpret_cast<float4*>(&g_X1[(size_t)row * 16]);
        o[0] = make_float4(acc[0],  acc[1],  acc[2],  acc[3]);
        o[1] = make_float4(acc[4],  acc[5],  acc[6],  acc[7]);
        o[2] = make_float4(acc[8],  acc[9],  acc[10], acc[11]);
        o[3] = make_float4(acc[12], acc[13], acc[14], acc[15]);
    }
}

// ---------------------------------------------------------------------------
// vectorized float atomic-add (sm_90+)
// ---------------------------------------------------------------------------
__device__ __forceinline__ void red_add_v4(float* p, float a, float b, float c,
                                           float d) {
    unsigned long long g = __cvta_generic_to_global(p);
    asm volatile("red.global.add.v4.f32 [%0], {%1,%2,%3,%4};"
                 :: "l"(g), "f"(a), "f"(b), "f"(c), "f"(d)
                 : "memory");
}

// ---------------------------------------------------------------------------
// K2: Y1 += vals[e] * X1[cols[e]]   (16 channels, thread per edge)
// ---------------------------------------------------------------------------
__global__ void spmm1_kernel(const int* __restrict__ rows,
                             const int* __restrict__ cols,
                             const float* __restrict__ vals, int nnz) {
    int e = blockIdx.x * blockDim.x + threadIdx.x;
    if (e >= nnz) return;
    int   r = rows[e];
    int   c = cols[e];
    float v = vals[e];
    const float4* xs = reinterpret_cast<const float4*>(&g_X1[(size_t)c * 16]);
    float* yd = &g_Y1[(size_t)r * 16];
#pragma unroll
    for (int j = 0; j < 4; j++) {
        float4 x = xs[j];
        red_add_v4(yd + 4 * j, v * x.x, v * x.y, v * x.z, v * x.w);
    }
}

// ---------------------------------------------------------------------------
// K3: Y2 += vals[e] * relu(Y1[cols[e]] + b1)  (bias+relu fused into gather)
// ---------------------------------------------------------------------------
__global__ void spmm2_kernel(const int* __restrict__ rows,
                             const int* __restrict__ cols,
                             const float* __restrict__ vals,
                             const float* __restrict__ b1, int nnz) {
    int e = blockIdx.x * blockDim.x + threadIdx.x;
    if (e >= nnz) return;
    int   r = rows[e];
    int   c = cols[e];
    float v = vals[e];
    const float4* bb = reinterpret_cast<const float4*>(b1);
    const float4* xs = reinterpret_cast<const float4*>(&g_Y1[(size_t)c * 16]);
    float* yd = &g_Y2[(size_t)r * 16];
#pragma unroll
    for (int j = 0; j < 4; j++) {
        float4 x = xs[j];
        float4 b = bb[j];   // L1-cached broadcast
        float z0 = fmaxf(x.x + b.x, 0.f);
        float z1 = fmaxf(x.y + b.y, 0.f);
        float z2 = fmaxf(x.z + b.z, 0.f);
        float z3 = fmaxf(x.w + b.w, 0.f);
        red_add_v4(yd + 4 * j, v * z0, v * z1, v * z2, v * z3);
    }
}

// ---------------------------------------------------------------------------
// K4: out = log_softmax(relu(Y2 @ W2 + b2))  — thread per row
// ---------------------------------------------------------------------------
__global__ void epilogue_kernel(const float* __restrict__ W2,
                                const float* __restrict__ b2,
                                float* __restrict__ out, int n) {
    __shared__ float sW[H1Q * CQ];
    __shared__ float sB[CQ];
    for (int i = threadIdx.x; i < H1Q * CQ; i += blockDim.x) sW[i] = W2[i];
    for (int i = threadIdx.x; i < CQ; i += blockDim.x) sB[i] = b2[i];
    __syncthreads();

    int row = blockIdx.x * blockDim.x + threadIdx.x;
    if (row >= n) return;

    float y[16];
    const float4* ys = reinterpret_cast<const float4*>(&g_Y2[(size_t)row * 16]);
#pragma unroll
    for (int j = 0; j < 4; j++) {
        float4 v = ys[j];
        y[4 * j + 0] = v.x; y[4 * j + 1] = v.y;
        y[4 * j + 2] = v.z; y[4 * j + 3] = v.w;
    }

    float t[CQ];
#pragma unroll
    for (int c = 0; c < CQ; c++) t[c] = sB[c];
#pragma unroll
    for (int k = 0; k < H1Q; k++) {
        float h = y[k];
#pragma unroll
        for (int c = 0; c < CQ; c++) t[c] = fmaf(h, sW[k * CQ + c], t[c]);
    }

    float m = 0.f;  // relu() output floor is 0
#pragma unroll
    for (int c = 0; c < CQ; c++) {
        t[c] = fmaxf(t[c], 0.f);
        m = fmaxf(m, t[c]);
    }
    float s = 0.f;
#pragma unroll
    for (int c = 0; c < CQ; c++) s += __expf(t[c] - m);
    float l = __logf(s) + m;

    float* o = out + (size_t)row * CQ;
#pragma unroll
    for (int c = 0; c < CQ; c++) o[c] = t[c] - l;
}

// ---------------------------------------------------------------------------
// Inputs (metadata order): H, A_vals, W1, b1, W2, b2, A_rows, A_cols
// ---------------------------------------------------------------------------
extern "C" void kernel_launch(void* const* d_in, const int* in_sizes, int n_in,
                              void* d_out, int out_size) {
    const float* Hm     = (const float*)d_in[0];
    const float* A_vals = (const float*)d_in[1];
    const float* W1     = (const float*)d_in[2];
    const float* b1     = (const float*)d_in[3];
    const float* W2     = (const float*)d_in[4];
    const float* b2     = (const float*)d_in[5];
    const int*   A_rows = (const int*)d_in[6];
    const int*   A_cols = (const int*)d_in[7];

    int n   = in_sizes[0] / DQ;
    int nnz = in_sizes[1];
    float* out = (float*)d_out;

    zero_kernel<<<592, 256>>>((n * H1Q) / 4);
    gemm1_kernel<<<(n + 3) / 4, 128>>>(Hm, W1, n);
    spmm1_kernel<<<(nnz + 255) / 256, 256>>>(A_rows, A_cols, A_vals, nnz);
    spmm2_kernel<<<(nnz + 255) / 256, 256>>>(A_rows, A_cols, A_vals, b1, nnz);
    epilogue_kernel<<<(n + 255) / 256, 256>>>(W2, b2, out, n);
}

// round 2
// speedup vs baseline: 1.5543x; 1.5543x over previous
#include <cuda_runtime.h>

#define DQ    512
#define H1Q   16
#define CQ    40
#define N_MAX 100000
#define NNZ_MAX 3200000
#define SCAN_B 1024
#define NBLK_SCAN ((N_MAX + SCAN_B - 1) / SCAN_B)   // 98

// ------------------------------ scratch (device globals) -------------------
__device__ float g_X1[N_MAX * H1Q];          // H @ W1
__device__ float g_Y1[N_MAX * H1Q];          // A @ X1
__device__ float g_Y2[N_MAX * H1Q];          // A @ relu(Y1 + b1)
__device__ int   g_cnt[N_MAX];               // row degree
__device__ int   g_ptr[N_MAX];               // CSR row pointer (exclusive)
__device__ int   g_cur[N_MAX];               // scatter cursor
__device__ int   g_part[NBLK_SCAN];          // scan block partials
__device__ int   g_part_sc[NBLK_SCAN];       // scanned partials
__device__ int2  g_edges[NNZ_MAX];           // packed {col, val_bits} in CSR order

// ------------------------------ CSR build ----------------------------------
__global__ void zero_cnt_kernel(int n) {
    int i = blockIdx.x * blockDim.x + threadIdx.x;
    if (i < n) g_cnt[i] = 0;
}

__global__ void hist_kernel(const int* __restrict__ rows, int nnz) {
    int e = blockIdx.x * blockDim.x + threadIdx.x;
    if (e < nnz) atomicAdd(&g_cnt[rows[e]], 1);
}

// per-block inclusive scan -> exclusive-within-block into g_ptr, totals to g_part
__global__ void scan1_kernel(int n) {
    __shared__ int s[SCAN_B];
    int tid = threadIdx.x;
    int i = blockIdx.x * SCAN_B + tid;
    int v = (i < n) ? g_cnt[i] : 0;
    s[tid] = v;
    __syncthreads();
#pragma unroll
    for (int off = 1; off < SCAN_B; off <<= 1) {
        int t = 0;
        if (tid >= off) t = s[tid - off];
        __syncthreads();
        if (tid >= off) s[tid] += t;
        __syncthreads();
    }
    if (i < n) g_ptr[i] = s[tid] - v;      // exclusive within block
    if (tid == SCAN_B - 1) g_part[blockIdx.x] = s[SCAN_B - 1];
}

__global__ void scan2_kernel(int nb) {
    if (threadIdx.x == 0 && blockIdx.x == 0) {
        int run = 0;
        for (int b = 0; b < nb; b++) { g_part_sc[b] = run; run += g_part[b]; }
    }
}

__global__ void scan3_kernel(int n) {
    int i = blockIdx.x * blockDim.x + threadIdx.x;
    if (i < n) {
        int p = g_ptr[i] + g_part_sc[i >> 10];
        g_ptr[i] = p;
        g_cur[i] = p;
    }
}

__global__ void scatter_kernel(const int* __restrict__ rows,
                               const int* __restrict__ cols,
                               const float* __restrict__ vals, int nnz) {
    int e = blockIdx.x * blockDim.x + threadIdx.x;
    if (e >= nnz) return;
    int r = rows[e];
    int pos = atomicAdd(&g_cur[r], 1);
    g_edges[pos] = make_int2(cols[e], __float_as_int(vals[e]));
}

// ------------------------------ K1: X1 = H @ W1 -----------------------------
// Block = 128 threads (4 warps). Each lane owns 2 rows (r0, r0+32):
// warp covers 64 rows, block covers 256 rows. W1 in smem, read as broadcast
// float4 (conflict-free). H rows streamed per-lane via float4 (L1 absorbs the
// half-sector granularity).
__global__ void __launch_bounds__(128) gemm1_kernel(
        const float* __restrict__ Hm, const float* __restrict__ W1, int n) {
    __shared__ float4 sW[DQ][4];
    for (int i = threadIdx.x; i < DQ * 4; i += blockDim.x)
        (&sW[0][0])[i] = reinterpret_cast<const float4*>(W1)[i];
    __syncthreads();

    int warp = threadIdx.x >> 5;
    int lane = threadIdx.x & 31;
    int ra = (blockIdx.x * 4 + warp) * 64 + lane;   // row A
    int rb = ra + 32;                               // row B
    bool va = ra < n, vb = rb < n;

    float acc0[16], acc1[16];
#pragma unroll
    for (int c = 0; c < 16; c++) { acc0[c] = 0.f; acc1[c] = 0.f; }

    const float4* pa = reinterpret_cast<const float4*>(Hm + (size_t)(va ? ra : 0) * DQ);
    const float4* pb = reinterpret_cast<const float4*>(Hm + (size_t)(vb ? rb : 0) * DQ);

#pragma unroll 2
    for (int kq = 0; kq < DQ / 4; kq++) {
        float4 h4a = va ? pa[kq] : make_float4(0, 0, 0, 0);
        float4 h4b = vb ? pb[kq] : make_float4(0, 0, 0, 0);
        float ha[4] = {h4a.x, h4a.y, h4a.z, h4a.w};
        float hb[4] = {h4b.x, h4b.y, h4b.z, h4b.w};
#pragma unroll
        for (int j = 0; j < 4; j++) {
            int k = kq * 4 + j;
#pragma unroll
            for (int q = 0; q < 4; q++) {
                float4 w = sW[k][q];
                acc0[q * 4 + 0] = fmaf(ha[j], w.x, acc0[q * 4 + 0]);
                acc0[q * 4 + 1] = fmaf(ha[j], w.y, acc0[q * 4 + 1]);
                acc0[q * 4 + 2] = fmaf(ha[j], w.z, acc0[q * 4 + 2]);
                acc0[q * 4 + 3] = fmaf(ha[j], w.w, acc0[q * 4 + 3]);
                acc1[q * 4 + 0] = fmaf(hb[j], w.x, acc1[q * 4 + 0]);
                acc1[q * 4 + 1] = fmaf(hb[j], w.y, acc1[q * 4 + 1]);
                acc1[q * 4 + 2] = fmaf(hb[j], w.z, acc1[q * 4 + 2]);
                acc1[q * 4 + 3] = fmaf(hb[j], w.w, acc1[q * 4 + 3]);
            }
        }
    }

    if (va) {
        float4* o = reinterpret_cast<float4*>(&g_X1[(size_t)ra * 16]);
#pragma unroll
        for (int q = 0; q < 4; q++)
            o[q] = make_float4(acc0[q * 4], acc0[q * 4 + 1], acc0[q * 4 + 2], acc0[q * 4 + 3]);
    }
    if (vb) {
        float4* o = reinterpret_cast<float4*>(&g_Y2[0]);  // dummy init to please compiler
        o = reinterpret_cast<float4*>(&g_X1[(size_t)rb * 16]);
#pragma unroll
        for (int q = 0; q < 4; q++)
            o[q] = make_float4(acc1[q * 4], acc1[q * 4 + 1], acc1[q * 4 + 2], acc1[q * 4 + 3]);
    }
}

// ------------------------------ CSR SpMM ------------------------------------
// warp = 8 rows x 4 lanes; lane owns channel quad `sub`. Gather-only, register
// accumulate, single coalesced float4 store per lane. No atomics.
__global__ void spmm1_csr_kernel(int n) {
    int wg   = (blockIdx.x * blockDim.x + threadIdx.x) >> 5;
    int lane = threadIdx.x & 31;
    int rloc = lane >> 2, sub = lane & 3;
    int row  = wg * 8 + rloc;
    if (row >= n) return;

    int start = g_ptr[row];
    int deg   = g_cnt[row];
    const int2* ed = g_edges + start;

    float4 acc = make_float4(0, 0, 0, 0);
    int2 e = (deg > 0) ? ed[0] : make_int2(0, 0);
    for (int i = 0; i < deg; i++) {
        int2 cur = e;
        if (i + 1 < deg) e = ed[i + 1];
        float v = __int_as_float(cur.y);
        const float4 x = *reinterpret_cast<const float4*>(&g_X1[(size_t)cur.x * 16 + sub * 4]);
        acc.x = fmaf(v, x.x, acc.x);
        acc.y = fmaf(v, x.y, acc.y);
        acc.z = fmaf(v, x.z, acc.z);
        acc.w = fmaf(v, x.w, acc.w);
    }
    *reinterpret_cast<float4*>(&g_Y1[(size_t)row * 16 + sub * 4]) = acc;
}

__global__ void spmm2_csr_kernel(const float* __restrict__ b1, int n) {
    int wg   = (blockIdx.x * blockDim.x + threadIdx.x) >> 5;
    int lane = threadIdx.x & 31;
    int rloc = lane >> 2, sub = lane & 3;
    int row  = wg * 8 + rloc;
    if (row >= n) return;

    int start = g_ptr[row];
    int deg   = g_cnt[row];
    const int2* ed = g_edges + start;
    const float4 b = reinterpret_cast<const float4*>(b1)[sub];

    float4 acc = make_float4(0, 0, 0, 0);
    int2 e = (deg > 0) ? ed[0] : make_int2(0, 0);
    for (int i = 0; i < deg; i++) {
        int2 cur = e;
        if (i + 1 < deg) e = ed[i + 1];
        float v = __int_as_float(cur.y);
        const float4 x = *reinterpret_cast<const float4*>(&g_Y1[(size_t)cur.x * 16 + sub * 4]);
        float z0 = fmaxf(x.x + b.x, 0.f);
        float z1 = fmaxf(x.y + b.y, 0.f);
        float z2 = fmaxf(x.z + b.z, 0.f);
        float z3 = fmaxf(x.w + b.w, 0.f);
        acc.x = fmaf(v, z0, acc.x);
        acc.y = fmaf(v, z1, acc.y);
        acc.z = fmaf(v, z2, acc.z);
        acc.w = fmaf(v, z3, acc.w);
    }
    *reinterpret_cast<float4*>(&g_Y2[(size_t)row * 16 + sub * 4]) = acc;
}

// ------------------------------ K4: epilogue --------------------------------
__global__ void epilogue_kernel(const float* __restrict__ W2,
                                const float* __restrict__ b2,
                                float* __restrict__ out, int n) {
    __shared__ float sW[H1Q * CQ];
    __shared__ float sB[CQ];
    for (int i = threadIdx.x; i < H1Q * CQ; i += blockDim.x) sW[i] = W2[i];
    for (int i = threadIdx.x; i < CQ; i += blockDim.x) sB[i] = b2[i];
    __syncthreads();

    int row = blockIdx.x * blockDim.x + threadIdx.x;
    if (row >= n) return;

    float y[16];
    const float4* ys = reinterpret_cast<const float4*>(&g_Y2[(size_t)row * 16]);
#pragma unroll
    for (int j = 0; j < 4; j++) {
        float4 v = ys[j];
        y[4 * j + 0] = v.x; y[4 * j + 1] = v.y;
        y[4 * j + 2] = v.z; y[4 * j + 3] = v.w;
    }

    float t[CQ];
#pragma unroll
    for (int c = 0; c < CQ; c++) t[c] = sB[c];
#pragma unroll
    for (int k = 0; k < H1Q; k++) {
        float h = y[k];
#pragma unroll
        for (int c = 0; c < CQ; c++) t[c] = fmaf(h, sW[k * CQ + c], t[c]);
    }

    float m = 0.f;  // relu floor
#pragma unroll
    for (int c = 0; c < CQ; c++) {
        t[c] = fmaxf(t[c], 0.f);
        m = fmaxf(m, t[c]);
    }
    float s = 0.f;
#pragma unroll
    for (int c = 0; c < CQ; c++) s += __expf(t[c] - m);
    float l = __logf(s) + m;

    float* o = out + (size_t)row * CQ;
#pragma unroll
    for (int c = 0; c < CQ; c++) o[c] = t[c] - l;
}

// ---------------------------------------------------------------------------
// Inputs (metadata order): H, A_vals, W1, b1, W2, b2, A_rows, A_cols
// ---------------------------------------------------------------------------
extern "C" void kernel_launch(void* const* d_in, const int* in_sizes, int n_in,
                              void* d_out, int out_size) {
    const float* Hm     = (const float*)d_in[0];
    const float* A_vals = (const float*)d_in[1];
    const float* W1     = (const float*)d_in[2];
    const float* b1     = (const float*)d_in[3];
    const float* W2     = (const float*)d_in[4];
    const float* b2     = (const float*)d_in[5];
    const int*   A_rows = (const int*)d_in[6];
    const int*   A_cols = (const int*)d_in[7];

    int n   = in_sizes[0] / DQ;
    int nnz = in_sizes[1];
    float* out = (float*)d_out;

    int nb_scan = (n + SCAN_B - 1) / SCAN_B;

    // CSR build
    zero_cnt_kernel<<<(n + 255) / 256, 256>>>(n);
    hist_kernel<<<(nnz + 255) / 256, 256>>>(A_rows, nnz);
    scan1_kernel<<<nb_scan, SCAN_B>>>(n);
    scan2_kernel<<<1, 32>>>(nb_scan);
    scan3_kernel<<<(n + 255) / 256, 256>>>(n);
    scatter_kernel<<<(nnz + 255) / 256, 256>>>(A_rows, A_cols, A_vals, nnz);

    // dense layer 1
    gemm1_kernel<<<(n + 255) / 256, 128>>>(Hm, W1, n);

    // sparse propagations (gather-only)
    int spmm_blocks = (n + 63) / 64;   // 8 warps/block * 8 rows/warp
    spmm1_csr_kernel<<<spmm_blocks, 256>>>(n);
    spmm2_csr_kernel<<<spmm_blocks, 256>>>(b1, n);

    // layer 2 dense + log_softmax
    epilogue_kernel<<<(n + 255) / 256, 256>>>(W2, b2, out, n);
}

// round 3
// speedup vs baseline: 1.9358x; 1.2454x over previous
#include <cuda_runtime.h>

typedef unsigned long long ull;

#define DQ    512
#define H1Q   16
#define CQ    40
#define N_MAX 100000
#define NNZ_MAX 3200000
#define SCAN_B 1024
#define NBLK_SCAN ((N_MAX + SCAN_B - 1) / SCAN_B)   // 98

// ------------------------------ scratch -------------------------------------
__device__ float g_X1[N_MAX * H1Q];          // H @ W1
__device__ float g_Z [N_MAX * H1Q];          // relu(A @ X1 + b1)
__device__ int   g_cnt[N_MAX];
__device__ int   g_ptr[N_MAX];
__device__ int   g_cur[N_MAX];
__device__ int   g_part[NBLK_SCAN];
__device__ int   g_part_sc[NBLK_SCAN];
__device__ int2  g_edges[NNZ_MAX];           // {col, val_bits} CSR-ordered

// ------------------------------ f32x2 helpers --------------------------------
__device__ __forceinline__ ull fma2(ull a, ull b, ull c) {
    ull d;
    asm("fma.rn.f32x2 %0, %1, %2, %3;" : "=l"(d) : "l"(a), "l"(b), "l"(c));
    return d;
}
__device__ __forceinline__ ull pack2(float x) {
    ull d;
    asm("mov.b64 %0, {%1, %1};" : "=l"(d) : "f"(x));
    return d;
}
__device__ __forceinline__ float2 unpack2(ull v) {
    float a, b;
    asm("mov.b64 {%0, %1}, %2;" : "=f"(a), "=f"(b) : "l"(v));
    return make_float2(a, b);
}

// ------------------------------ CSR build -----------------------------------
__global__ void zero_cnt_kernel(int n) {
    int i = blockIdx.x * blockDim.x + threadIdx.x;
    if (i < n) g_cnt[i] = 0;
}

__global__ void hist_kernel(const int* __restrict__ rows, int nnz) {
    int e = blockIdx.x * blockDim.x + threadIdx.x;
    if (e < nnz) atomicAdd(&g_cnt[rows[e]], 1);
}

__global__ void scan1_kernel(int n) {
    __shared__ int s[SCAN_B];
    int tid = threadIdx.x;
    int i = blockIdx.x * SCAN_B + tid;
    int v = (i < n) ? g_cnt[i] : 0;
    s[tid] = v;
    __syncthreads();
#pragma unroll
    for (int off = 1; off < SCAN_B; off <<= 1) {
        int t = 0;
        if (tid >= off) t = s[tid - off];
        __syncthreads();
        if (tid >= off) s[tid] += t;
        __syncthreads();
    }
    if (i < n) g_ptr[i] = s[tid] - v;
    if (tid == SCAN_B - 1) g_part[blockIdx.x] = s[SCAN_B - 1];
}

// parallel scan of the <=128 block partials (Hillis-Steele)
__global__ void scan2_kernel(int nb) {
    __shared__ int s[128];
    int t = threadIdx.x;
    int v = (t < nb) ? g_part[t] : 0;
    s[t] = v;
    __syncthreads();
#pragma unroll
    for (int off = 1; off < 128; off <<= 1) {
        int u = 0;
        if (t >= off) u = s[t - off];
        __syncthreads();
        if (t >= off) s[t] += u;
        __syncthreads();
    }
    if (t < nb) g_part_sc[t] = s[t] - v;   // exclusive
}

__global__ void scan3_kernel(int n) {
    int i = blockIdx.x * blockDim.x + threadIdx.x;
    if (i < n) {
        int p = g_ptr[i] + g_part_sc[i >> 10];
        g_ptr[i] = p;
        g_cur[i] = p;
    }
}

// ------------------------------ fused gemm1 + scatter ------------------------
// blockIdx < gemm_blocks : X1 = H @ W1 (256 thr = 8 warps, 64 rows/warp,
//   512 rows/block, FFMA2 packed math, W1 broadcast from smem)
// else                   : CSR scatter of edges (256 edges/block)
__global__ void __launch_bounds__(256) gemm_scatter_kernel(
        const float* __restrict__ Hm, const float* __restrict__ W1,
        const int* __restrict__ rows, const int* __restrict__ cols,
        const float* __restrict__ vals, int n, int nnz, int gemm_blocks) {
    __shared__ ull sW2[DQ * 8];   // 32KB: [k][pair] = {W1[k][2p], W1[k][2p+1]}

    if ((int)blockIdx.x < gemm_blocks) {
        for (int i = threadIdx.x; i < DQ * 8; i += blockDim.x)
            sW2[i] = reinterpret_cast<const ull*>(W1)[i];
        __syncthreads();

        int warp = threadIdx.x >> 5;
        int lane = threadIdx.x & 31;
        int ra = blockIdx.x * 512 + warp * 64 + lane;
        int rb = ra + 32;
        bool va = ra < n, vb = rb < n;

        ull acc0[8], acc1[8];
        ull z = pack2(0.f);
#pragma unroll
        for (int p = 0; p < 8; p++) { acc0[p] = z; acc1[p] = z; }

        const float4* pa = reinterpret_cast<const float4*>(Hm + (size_t)(va ? ra : 0) * DQ);
        const float4* pb = reinterpret_cast<const float4*>(Hm + (size_t)(vb ? rb : 0) * DQ);
        const ulonglong2* wv = reinterpret_cast<const ulonglong2*>(sW2);

#pragma unroll 4
        for (int kq = 0; kq < DQ / 4; kq++) {
            float4 h4a = va ? pa[kq] : make_float4(0, 0, 0, 0);
            float4 h4b = vb ? pb[kq] : make_float4(0, 0, 0, 0);
            float ha[4] = {h4a.x, h4a.y, h4a.z, h4a.w};
            float hb[4] = {h4b.x, h4b.y, h4b.z, h4b.w};
#pragma unroll
            for (int j = 0; j < 4; j++) {
                int k = kq * 4 + j;
                ull hha = pack2(ha[j]);
                ull hhb = pack2(hb[j]);
#pragma unroll
                for (int q = 0; q < 4; q++) {
                    ulonglong2 w = wv[k * 4 + q];
                    acc0[2 * q + 0] = fma2(hha, w.x, acc0[2 * q + 0]);
                    acc0[2 * q + 1] = fma2(hha, w.y, acc0[2 * q + 1]);
                    acc1[2 * q + 0] = fma2(hhb, w.x, acc1[2 * q + 0]);
                    acc1[2 * q + 1] = fma2(hhb, w.y, acc1[2 * q + 1]);
                }
            }
        }

        if (va) {
            ull* o = reinterpret_cast<ull*>(&g_X1[(size_t)ra * 16]);
#pragma unroll
            for (int p = 0; p < 8; p++) o[p] = acc0[p];
        }
        if (vb) {
            ull* o = reinterpret_cast<ull*>(&g_X1[(size_t)rb * 16]);
#pragma unroll
            for (int p = 0; p < 8; p++) o[p] = acc1[p];
        }
    } else {
        int e = (blockIdx.x - gemm_blocks) * blockDim.x + threadIdx.x;
        if (e < nnz) {
            int r = rows[e];
            int pos = atomicAdd(&g_cur[r], 1);
            g_edges[pos] = make_int2(cols[e], __float_as_int(vals[e]));
        }
    }
}

// ------------------------------ SpMM 1 --------------------------------------
// warp = 8 rows x 4 lanes (lane owns a float4 channel quad); gather-only.
// Writes Z = relu(A@X1 + b1) so layer-2 gathers need no per-edge bias/relu.
__global__ void spmm1_kernel(const float* __restrict__ b1, int n) {
    int wg   = (blockIdx.x * blockDim.x + threadIdx.x) >> 5;
    int lane = threadIdx.x & 31;
    int rloc = lane >> 2, sub = lane & 3;
    int row  = wg * 8 + rloc;
    if (row >= n) return;

    int start = g_ptr[row];
    int deg   = g_cnt[row];
    const int2* ed = g_edges + start;
    const float4 b = reinterpret_cast<const float4*>(b1)[sub];

    float4 acc = make_float4(0, 0, 0, 0);
#pragma unroll 2
    for (int i = 0; i < deg; i++) {
        int2 e = ed[i];
        float v = __int_as_float(e.y);
        const float4 x = *reinterpret_cast<const float4*>(
            &g_X1[(size_t)e.x * 16 + sub * 4]);
        acc.x = fmaf(v, x.x, acc.x);
        acc.y = fmaf(v, x.y, acc.y);
        acc.z = fmaf(v, x.z, acc.z);
        acc.w = fmaf(v, x.w, acc.w);
    }
    float4 zz;
    zz.x = fmaxf(acc.x + b.x, 0.f);
    zz.y = fmaxf(acc.y + b.y, 0.f);
    zz.z = fmaxf(acc.z + b.z, 0.f);
    zz.w = fmaxf(acc.w + b.w, 0.f);
    *reinterpret_cast<float4*>(&g_Z[(size_t)row * 16 + sub * 4]) = zz;
}

// ------------------------------ SpMM 2 + epilogue ----------------------------
// Same gather structure on Z; row results staged in smem, then 64 threads do
// the W2 GEMM + bias + relu + log_softmax and store out directly.
__global__ void __launch_bounds__(256) spmm2_epi_kernel(
        const float* __restrict__ W2, const float* __restrict__ b2,
        float* __restrict__ out, int n) {
    __shared__ float sY[64 * 17];          // [rloc][17] pad: conflict-free scalar reads
    __shared__ float sW[H1Q * CQ];
    __shared__ float sB[CQ];

    for (int i = threadIdx.x; i < H1Q * CQ; i += blockDim.x) sW[i] = W2[i];
    if (threadIdx.x < CQ) sB[threadIdx.x] = b2[threadIdx.x];

    int warp  = threadIdx.x >> 5;
    int lane  = threadIdx.x & 31;
    int rloc  = warp * 8 + (lane >> 2);    // 0..63 within block
    int sub   = lane & 3;
    int rbase = blockIdx.x * 64;
    int row   = rbase + rloc;

    float4 acc = make_float4(0, 0, 0, 0);
    if (row < n) {
        int start = g_ptr[row];
        int deg   = g_cnt[row];
        const int2* ed = g_edges + start;
#pragma unroll 2
        for (int i = 0; i < deg; i++) {
            int2 e = ed[i];
            float v = __int_as_float(e.y);
            const float4 x = *reinterpret_cast<const float4*>(
                &g_Z[(size_t)e.x * 16 + sub * 4]);
            acc.x = fmaf(v, x.x, acc.x);
            acc.y = fmaf(v, x.y, acc.y);
            acc.z = fmaf(v, x.z, acc.z);
            acc.w = fmaf(v, x.w, acc.w);
        }
    }
    float* sy = &sY[rloc * 17 + sub * 4];
    sy[0] = acc.x; sy[1] = acc.y; sy[2] = acc.z; sy[3] = acc.w;
    __syncthreads();

    int t = threadIdx.x;
    if (t < 64 && rbase + t < n) {
        float y[16];
#pragma unroll
        for (int k = 0; k < 16; k++) y[k] = sY[t * 17 + k];

        float o[CQ];
#pragma unroll
        for (int c = 0; c < CQ; c++) o[c] = sB[c];
#pragma unroll
        for (int k = 0; k < H1Q; k++) {
            float h = y[k];
#pragma unroll
            for (int c = 0; c < CQ; c++) o[c] = fmaf(h, sW[k * CQ + c], o[c]);
        }
        float m = 0.f;                      // relu floor
#pragma unroll
        for (int c = 0; c < CQ; c++) {
            o[c] = fmaxf(o[c], 0.f);
            m = fmaxf(m, o[c]);
        }
        float s = 0.f;
#pragma unroll
        for (int c = 0; c < CQ; c++) s += __expf(o[c] - m);
        float l = __logf(s) + m;

        float4* op = reinterpret_cast<float4*>(out + (size_t)(rbase + t) * CQ);
#pragma unroll
        for (int q = 0; q < CQ / 4; q++)
            op[q] = make_float4(o[4 * q] - l, o[4 * q + 1] - l,
                                o[4 * q + 2] - l, o[4 * q + 3] - l);
    }
}

// ---------------------------------------------------------------------------
// Inputs (metadata order): H, A_vals, W1, b1, W2, b2, A_rows, A_cols
// ---------------------------------------------------------------------------
extern "C" void kernel_launch(void* const* d_in, const int* in_sizes, int n_in,
                              void* d_out, int out_size) {
    const float* Hm     = (const float*)d_in[0];
    const float* A_vals = (const float*)d_in[1];
    const float* W1     = (const float*)d_in[2];
    const float* b1     = (const float*)d_in[3];
    const float* W2     = (const float*)d_in[4];
    const float* b2     = (const float*)d_in[5];
    const int*   A_rows = (const int*)d_in[6];
    const int*   A_cols = (const int*)d_in[7];

    int n   = in_sizes[0] / DQ;
    int nnz = in_sizes[1];
    float* out = (float*)d_out;

    int nb_scan = (n + SCAN_B - 1) / SCAN_B;

    zero_cnt_kernel<<<(n + 255) / 256, 256>>>(n);
    hist_kernel<<<(nnz + 255) / 256, 256>>>(A_rows, nnz);
    scan1_kernel<<<nb_scan, SCAN_B>>>(n);
    scan2_kernel<<<1, 128>>>(nb_scan);
    scan3_kernel<<<(n + 255) / 256, 256>>>(n);

    int gemm_blocks    = (n + 511) / 512;
    int scatter_blocks = (nnz + 255) / 256;
    gemm_scatter_kernel<<<gemm_blocks + scatter_blocks, 256>>>(
        Hm, W1, A_rows, A_cols, A_vals, n, nnz, gemm_blocks);

    spmm1_kernel<<<(n + 63) / 64, 256>>>(b1, n);
    spmm2_epi_kernel<<<(n + 63) / 64, 256>>>(W2, b2, out, n);
}

// round 4
// speedup vs baseline: 1.9684x; 1.0168x over previous
#include <cuda_runtime.h>
#include <cuda_fp16.h>

typedef unsigned long long ull;

#define DQ    512
#define H1Q   16
#define CQ    40
#define N_MAX 100000
#define NNZ_MAX 3200000
#define SCAN_B 1024
#define NBLK_SCAN ((N_MAX + SCAN_B - 1) / SCAN_B)   // 98

// ------------------------------ scratch -------------------------------------
__device__ uint2 g_X1h[N_MAX * 4];           // H @ W1, fp16 (4 halves per uint2)
__device__ uint2 g_Zh [N_MAX * 4];           // relu(A @ X1 + b1), fp16
__device__ int   g_cnt[N_MAX];
__device__ int   g_ptr[N_MAX];
__device__ int   g_cur[N_MAX];
__device__ int   g_part[NBLK_SCAN];
__device__ int2  g_edges[NNZ_MAX];           // {col, val_bits} CSR-ordered

// ------------------------------ f32x2 helpers --------------------------------
__device__ __forceinline__ ull fma2(ull a, ull b, ull c) {
    ull d;
    asm("fma.rn.f32x2 %0, %1, %2, %3;" : "=l"(d) : "l"(a), "l"(b), "l"(c));
    return d;
}
__device__ __forceinline__ ull pack2(float x) {
    ull d;
    asm("mov.b64 %0, {%1, %1};" : "=l"(d) : "f"(x));
    return d;
}
__device__ __forceinline__ float2 unpack2(ull v) {
    float a, b;
    asm("mov.b64 {%0, %1}, %2;" : "=f"(a), "=f"(b) : "l"(v));
    return make_float2(a, b);
}
// pack two f32x2 accumulators (channels 2p,2p+1) into one uint of 2 halves
__device__ __forceinline__ unsigned h2pack(ull v) {
    float2 f = unpack2(v);
    __half2 h = __float22half2_rn(f);
    return *reinterpret_cast<unsigned*>(&h);
}
__device__ __forceinline__ float2 h2unpack(unsigned u) {
    __half2 h = *reinterpret_cast<__half2*>(&u);
    return __half22float2(h);
}

// ------------------------------ CSR build -----------------------------------
__global__ void hist_kernel(const int* __restrict__ rows, int nnz) {
    int e = blockIdx.x * blockDim.x + threadIdx.x;
    if (e < nnz) atomicAdd(&g_cnt[rows[e]], 1);
}

__global__ void scan1_kernel(int n) {
    __shared__ int s[SCAN_B];
    int tid = threadIdx.x;
    int i = blockIdx.x * SCAN_B + tid;
    int v = (i < n) ? g_cnt[i] : 0;
    s[tid] = v;
    __syncthreads();
#pragma unroll
    for (int off = 1; off < SCAN_B; off <<= 1) {
        int t = 0;
        if (tid >= off) t = s[tid - off];
        __syncthreads();
        if (tid >= off) s[tid] += t;
        __syncthreads();
    }
    if (i < n) g_ptr[i] = s[tid] - v;   // exclusive within block
    if (tid == SCAN_B - 1) g_part[blockIdx.x] = s[SCAN_B - 1];
}

// fused: scan the <=128 block partials in smem, then finalize ptr/cur
__global__ void scan23_kernel(int n, int nb) {
    __shared__ int s[128];
    int tid = threadIdx.x;
    if (tid < 128) s[tid] = (tid < nb) ? g_part[tid] : 0;
    __syncthreads();
#pragma unroll
    for (int off = 1; off < 128; off <<= 1) {
        int u = 0;
        if (tid < 128 && tid >= off) u = s[tid - off];
        __syncthreads();
        if (tid < 128 && tid >= off) s[tid] += u;
        __syncthreads();
    }
    int i = blockIdx.x * blockDim.x + tid;
    if (i < n) {
        int blk = i >> 10;
        int base = (blk == 0) ? 0 : s[blk - 1];   // exclusive prefix of partials
        int p = g_ptr[i] + base;
        g_ptr[i] = p;
        g_cur[i] = p;
    }
}

// ------------------------------ fused gemm1 + scatter ------------------------
__global__ void __launch_bounds__(256) gemm_scatter_kernel(
        const float* __restrict__ Hm, const float* __restrict__ W1,
        const int* __restrict__ rows, const int* __restrict__ cols,
        const float* __restrict__ vals, int n, int nnz, int gemm_blocks) {
    __shared__ ull sW2[DQ * 8];   // 32KB

    if ((int)blockIdx.x < gemm_blocks) {
        for (int i = threadIdx.x; i < DQ * 8; i += blockDim.x)
            sW2[i] = reinterpret_cast<const ull*>(W1)[i];
        __syncthreads();

        int warp = threadIdx.x >> 5;
        int lane = threadIdx.x & 31;
        int ra = blockIdx.x * 512 + warp * 64 + lane;
        int rb = ra + 32;
        bool va = ra < n, vb = rb < n;

        ull acc0[8], acc1[8];
        ull z = pack2(0.f);
#pragma unroll
        for (int p = 0; p < 8; p++) { acc0[p] = z; acc1[p] = z; }

        const float4* pa = reinterpret_cast<const float4*>(Hm + (size_t)(va ? ra : 0) * DQ);
        const float4* pb = reinterpret_cast<const float4*>(Hm + (size_t)(vb ? rb : 0) * DQ);
        const ulonglong2* wv = reinterpret_cast<const ulonglong2*>(sW2);

#pragma unroll 4
        for (int kq = 0; kq < DQ / 4; kq++) {
            float4 h4a = va ? pa[kq] : make_float4(0, 0, 0, 0);
            float4 h4b = vb ? pb[kq] : make_float4(0, 0, 0, 0);
            float ha[4] = {h4a.x, h4a.y, h4a.z, h4a.w};
            float hb[4] = {h4b.x, h4b.y, h4b.z, h4b.w};
#pragma unroll
            for (int j = 0; j < 4; j++) {
                int k = kq * 4 + j;
                ull hha = pack2(ha[j]);
                ull hhb = pack2(hb[j]);
#pragma unroll
                for (int q = 0; q < 4; q++) {
                    ulonglong2 w = wv[k * 4 + q];
                    acc0[2 * q + 0] = fma2(hha, w.x, acc0[2 * q + 0]);
                    acc0[2 * q + 1] = fma2(hha, w.y, acc0[2 * q + 1]);
                    acc1[2 * q + 0] = fma2(hhb, w.x, acc1[2 * q + 0]);
                    acc1[2 * q + 1] = fma2(hhb, w.y, acc1[2 * q + 1]);
                }
            }
        }

        if (va) {
            uint2* o = &g_X1h[(size_t)ra * 4];
#pragma unroll
            for (int q = 0; q < 4; q++)
                o[q] = make_uint2(h2pack(acc0[2 * q]), h2pack(acc0[2 * q + 1]));
        }
        if (vb) {
            uint2* o = &g_X1h[(size_t)rb * 4];
#pragma unroll
            for (int q = 0; q < 4; q++)
                o[q] = make_uint2(h2pack(acc1[2 * q]), h2pack(acc1[2 * q + 1]));
        }
    } else {
        int e = (blockIdx.x - gemm_blocks) * blockDim.x + threadIdx.x;
        if (e < nnz) {
            int r = rows[e];
            int pos = atomicAdd(&g_cur[r], 1);
            g_edges[pos] = make_int2(cols[e], __float_as_int(vals[e]));
        }
    }
}

// ------------------------------ SpMM 1 --------------------------------------
// warp = 8 rows x 4 lanes; lane owns 4 channels (one uint2 of halves).
__global__ void spmm1_kernel(const float* __restrict__ b1, int n) {
    int wg   = (blockIdx.x * blockDim.x + threadIdx.x) >> 5;
    int lane = threadIdx.x & 31;
    int rloc = lane >> 2, sub = lane & 3;
    int row  = wg * 8 + rloc;
    if (row >= n) return;

    int start = g_ptr[row];
    int deg   = g_cnt[row];
    const int2* ed = g_edges + start;
    const float4 b = reinterpret_cast<const float4*>(b1)[sub];

    float4 acc = make_float4(0, 0, 0, 0);
#pragma unroll 2
    for (int i = 0; i < deg; i++) {
        int2 e = ed[i];
        float v = __int_as_float(e.y);
        uint2 xh = g_X1h[(size_t)e.x * 4 + sub];
        float2 x0 = h2unpack(xh.x);
        float2 x1 = h2unpack(xh.y);
        acc.x = fmaf(v, x0.x, acc.x);
        acc.y = fmaf(v, x0.y, acc.y);
        acc.z = fmaf(v, x1.x, acc.z);
        acc.w = fmaf(v, x1.y, acc.w);
    }
    float2 z0 = make_float2(fmaxf(acc.x + b.x, 0.f), fmaxf(acc.y + b.y, 0.f));
    float2 z1 = make_float2(fmaxf(acc.z + b.z, 0.f), fmaxf(acc.w + b.w, 0.f));
    __half2 h0 = __float22half2_rn(z0);
    __half2 h1 = __float22half2_rn(z1);
    g_Zh[(size_t)row * 4 + sub] =
        make_uint2(*reinterpret_cast<unsigned*>(&h0), *reinterpret_cast<unsigned*>(&h1));
}

// ------------------------------ SpMM 2 + epilogue ----------------------------
__global__ void __launch_bounds__(256) spmm2_epi_kernel(
        const float* __restrict__ W2, const float* __restrict__ b2,
        float* __restrict__ out, int n) {
    __shared__ float sY[64 * 17];
    __shared__ float sW[H1Q * CQ];
    __shared__ float sB[CQ];

    for (int i = threadIdx.x; i < H1Q * CQ; i += blockDim.x) sW[i] = W2[i];
    if (threadIdx.x < CQ) sB[threadIdx.x] = b2[threadIdx.x];

    int warp  = threadIdx.x >> 5;
    int lane  = threadIdx.x & 31;
    int rloc  = warp * 8 + (lane >> 2);
    int sub   = lane & 3;
    int rbase = blockIdx.x * 64;
    int row   = rbase + rloc;

    float4 acc = make_float4(0, 0, 0, 0);
    if (row < n) {
        int start = g_ptr[row];
        int deg   = g_cnt[row];
        const int2* ed = g_edges + start;
#pragma unroll 2
        for (int i = 0; i < deg; i++) {
            int2 e = ed[i];
            float v = __int_as_float(e.y);
            uint2 xh = g_Zh[(size_t)e.x * 4 + sub];
            float2 x0 = h2unpack(xh.x);
            float2 x1 = h2unpack(xh.y);
            acc.x = fmaf(v, x0.x, acc.x);
            acc.y = fmaf(v, x0.y, acc.y);
            acc.z = fmaf(v, x1.x, acc.z);
            acc.w = fmaf(v, x1.y, acc.w);
        }
    }
    float* sy = &sY[rloc * 17 + sub * 4];
    sy[0] = acc.x; sy[1] = acc.y; sy[2] = acc.z; sy[3] = acc.w;
    __syncthreads();

    int t = threadIdx.x;
    if (t < 64 && rbase + t < n) {
        float y[16];
#pragma unroll
        for (int k = 0; k < 16; k++) y[k] = sY[t * 17 + k];

        float o[CQ];
#pragma unroll
        for (int c = 0; c < CQ; c++) o[c] = sB[c];
#pragma unroll
        for (int k = 0; k < H1Q; k++) {
            float h = y[k];
#pragma unroll
            for (int c = 0; c < CQ; c++) o[c] = fmaf(h, sW[k * CQ + c], o[c]);
        }
        float m = 0.f;
#pragma unroll
        for (int c = 0; c < CQ; c++) {
            o[c] = fmaxf(o[c], 0.f);
            m = fmaxf(m, o[c]);
        }
        float s = 0.f;
#pragma unroll
        for (int c = 0; c < CQ; c++) s += __expf(o[c] - m);
        float l = __logf(s) + m;

        float4* op = reinterpret_cast<float4*>(out + (size_t)(rbase + t) * CQ);
#pragma unroll
        for (int q = 0; q < CQ / 4; q++)
            op[q] = make_float4(o[4 * q] - l, o[4 * q + 1] - l,
                                o[4 * q + 2] - l, o[4 * q + 3] - l);
    }
}

// ---------------------------------------------------------------------------
// Inputs (metadata order): H, A_vals, W1, b1, W2, b2, A_rows, A_cols
// ---------------------------------------------------------------------------
extern "C" void kernel_launch(void* const* d_in, const int* in_sizes, int n_in,
                              void* d_out, int out_size) {
    const float* Hm     = (const float*)d_in[0];
    const float* A_vals = (const float*)d_in[1];
    const float* W1     = (const float*)d_in[2];
    const float* b1     = (const float*)d_in[3];
    const float* W2     = (const float*)d_in[4];
    const float* b2     = (const float*)d_in[5];
    const int*   A_rows = (const int*)d_in[6];
    const int*   A_cols = (const int*)d_in[7];

    int n   = in_sizes[0] / DQ;
    int nnz = in_sizes[1];
    float* out = (float*)d_out;

    int nb_scan = (n + SCAN_B - 1) / SCAN_B;

    void* cnt_ptr = nullptr;
    cudaGetSymbolAddress(&cnt_ptr, g_cnt);
    cudaMemsetAsync(cnt_ptr, 0, (size_t)n * sizeof(int), 0);

    hist_kernel<<<(nnz + 255) / 256, 256>>>(A_rows, nnz);
    scan1_kernel<<<nb_scan, SCAN_B>>>(n);
    scan23_kernel<<<(n + 255) / 256, 256>>>(n, nb_scan);

    int gemm_blocks    = (n + 511) / 512;
    int scatter_blocks = (nnz + 255) / 256;
    gemm_scatter_kernel<<<gemm_blocks + scatter_blocks, 256>>>(
        Hm, W1, A_rows, A_cols, A_vals, n, nnz, gemm_blocks);

    spmm1_kernel<<<(n + 63) / 64, 256>>>(b1, n);
    spmm2_epi_kernel<<<(n + 63) / 64, 256>>>(W2, b2, out, n);
}